// round 17
// baseline (speedup 1.0000x reference)
#include <cuda_runtime.h>
#include <cstdint>

#define NN 50000
#define EE 800000
#define RR 8
#define HD 128
#define NG 2            // graphs

#define GM 64
#define PW 68           // smem row stride in u32 (fp16 pairs): 68 % 32 == 4 -> conflict-free
#define MBLK ((NN + GM - 1) / GM)
#define GEMM_SMEM ((GM * PW + HD * PW) * 4)   // 17408 + 34816 = 52224 -> 3 CTAs/SM

// ---------------- scratch (device globals; no allocation allowed) ----------
__device__ uint4 g_xt[(size_t)NG * RR * NN * 16];  // 204.8 MB xt fp16 [g][r][n][128]
__device__ float g_acc[(size_t)NG * NN * HD];      // 51.2 MB unnormalized agg
__device__ float g_denom[NG * NN];
__device__ float g_wq[NG * RR * HD];
__device__ float g_wk[NG * RR * HD];
__device__ float g_qi[NG * NN * RR];
__device__ float g_kj[NG * NN * RR];

// pack two f32 -> f16x2 (first arg in low half = first k element)
__device__ __forceinline__ uint32_t pack_f16x2(float lo, float hi) {
    uint32_t r;
    asm("cvt.rn.f16x2.f32 %0, %1, %2;" : "=r"(r) : "f"(hi), "f"(lo));
    return r;
}
// unpack f16x2 -> two f32
__device__ __forceinline__ float2 unpack_f16x2(uint32_t u) {
    float lo, hi;
    asm("{ .reg .b16 l, h;\n\t"
        "  mov.b32 {l, h}, %2;\n\t"
        "  cvt.f32.f16 %0, l;\n\t"
        "  cvt.f32.f16 %1, h; }"
        : "=f"(lo), "=f"(hi) : "r"(u));
    return make_float2(lo, hi);
}

// ---------------- zero acc + denom -----------------------------------------
__global__ void prep_kernel() {
    int i = blockIdx.x * blockDim.x + threadIdx.x;
    int stride = gridDim.x * blockDim.x;
    float4 z = make_float4(0.f, 0.f, 0.f, 0.f);
    float4* a4 = (float4*)g_acc;
    const int na4 = NG * NN * HD / 4;
    for (int j = i; j < na4; j += stride) a4[j] = z;
    for (int j = i; j < NG * NN; j += stride) g_denom[j] = 0.f;
}

// ---------------- Wq[r] = W_r @ q, Wk[r] = W_r @ k --------------------------
__global__ void wqwk_kernel(const float* __restrict__ W1, const float* __restrict__ q1,
                            const float* __restrict__ k1,
                            const float* __restrict__ W2, const float* __restrict__ q2,
                            const float* __restrict__ k2) {
    int graph = blockIdx.y;
    const float* W = graph ? W2 : W1;
    const float* q = graph ? q2 : q1;
    const float* k = graph ? k2 : k1;
    int w = (blockIdx.x * blockDim.x + threadIdx.x) >> 5;
    int lane = threadIdx.x & 31;
    if (w >= RR * HD) return;
    const float* row = W + (size_t)w * HD;
    float sq = 0.f, sk = 0.f;
#pragma unroll
    for (int j = lane; j < HD; j += 32) {
        float wv = row[j];
        sq += wv * q[j];
        sk += wv * k[j];
    }
#pragma unroll
    for (int o = 16; o; o >>= 1) {
        sq += __shfl_xor_sync(0xffffffffu, sq, o);
        sk += __shfl_xor_sync(0xffffffffu, sk, o);
    }
    if (lane == 0) {
        g_wq[graph * RR * HD + w] = sq;
        g_wk[graph * RR * HD + w] = sk;
    }
}

// ---------------- per-node logit tables: qi[n][r], kj[n][r] -----------------
__global__ void table_kernel(const float* __restrict__ x1,
                             const float* __restrict__ x2) {
    int graph = blockIdx.y;
    const float* x = graph ? x2 : x1;
    int n = (blockIdx.x * blockDim.x + threadIdx.x) >> 5;
    if (n >= NN) return;
    int lane = threadIdx.x & 31;
    float4 xv = ((const float4*)x)[(size_t)n * 32 + lane];
    const float4* wq4 = (const float4*)(g_wq + graph * RR * HD);
    const float4* wk4 = (const float4*)(g_wk + graph * RR * HD);
#pragma unroll
    for (int r = 0; r < RR; r++) {
        float4 wq = wq4[r * 32 + lane];
        float4 wk = wk4[r * 32 + lane];
        float sq = xv.x * wq.x + xv.y * wq.y + xv.z * wq.z + xv.w * wq.w;
        float sk = xv.x * wk.x + xv.y * wk.y + xv.z * wk.z + xv.w * wk.w;
#pragma unroll
        for (int o = 16; o; o >>= 1) {
            sq += __shfl_xor_sync(0xffffffffu, sq, o);
            sk += __shfl_xor_sync(0xffffffffu, sk, o);
        }
        if (lane == 0) {
            g_qi[(graph * NN + n) * RR + r] = sq;
            g_kj[(graph * NN + n) * RR + r] = sk;
        }
    }
}

// ---------------- xt[g][r] = x @ W_r  (fp16 mma.sync m16n8k16) --------------
// GM=64: A tile 17.4KB + full W_r^T 34.8KB = 52.2KB -> 3 CTAs/SM (24 warps).
// Warp tile 32x32 (acc 32 regs). launch_bounds(256,3): cap 85 >= natural.
__global__ __launch_bounds__(256, 3)
void xt_gemm(const float* __restrict__ x1, const float* __restrict__ x2,
             const float* __restrict__ W1, const float* __restrict__ W2) {
    extern __shared__ uint32_t sm[];
    uint32_t* As = sm;             // [64][PW]   x tile, fp16 pairs along k
    uint32_t* Bs = sm + GM * PW;   // [128 n][PW] W_r^T, fp16 pairs along k
    int graph = blockIdx.y;
    const float* x = graph ? x2 : x1;
    const float* W = graph ? W2 : W1;
    int m0 = blockIdx.x * GM;
    int tid = threadIdx.x;
    int wid = tid >> 5, lane = tid & 31;
    int warpM = wid >> 2;    // 0..1 -> 32-row slab
    int warpN = wid & 3;     // 0..3 -> 32-col slab
    int g = lane >> 2, t = lane & 3;

    // load A tile once, convert to fp16 pairs (k-contiguous)
    for (int idx = tid; idx < GM * 32; idx += 256) {
        int row = idx >> 5, c4 = idx & 31;
        int gm = m0 + row;
        float4 v = make_float4(0.f, 0.f, 0.f, 0.f);
        if (gm < NN) v = ((const float4*)x)[(size_t)gm * 32 + c4];
        uint2 u = make_uint2(pack_f16x2(v.x, v.y), pack_f16x2(v.z, v.w));
        *(uint2*)&As[row * PW + c4 * 2] = u;
    }

    for (int r = 0; r < RR; r++) {
        const float* Wr = W + (size_t)r * HD * HD;
        __syncthreads();   // Bs (prev r) fully consumed; As ready (r=0)
        // load W_r transposed: Bs[n][kp] = (W[2kp][n], W[2kp+1][n])
#pragma unroll
        for (int i = 0; i < 32; i++) {
            int idx = tid + i * 256;
            int n = idx & 127, kp = idx >> 7;
            float w0 = __ldg(&Wr[(size_t)(2 * kp) * HD + n]);
            float w1 = __ldg(&Wr[(size_t)(2 * kp + 1) * HD + n]);
            Bs[n * PW + kp] = pack_f16x2(w0, w1);
        }
        __syncthreads();

        float acc[2][4][4];
#pragma unroll
        for (int mt = 0; mt < 2; mt++)
#pragma unroll
            for (int nt = 0; nt < 4; nt++)
#pragma unroll
                for (int c = 0; c < 4; c++) acc[mt][nt][c] = 0.f;

#pragma unroll
        for (int ks = 0; ks < 8; ks++) {       // 8 K-steps of 16
            int kb = ks * 8;                   // u32 (pair) offset
            uint32_t a[2][4];
#pragma unroll
            for (int mt = 0; mt < 2; mt++) {
                int rb = warpM * 32 + mt * 16 + g;
                a[mt][0] = As[rb * PW + kb + t];
                a[mt][1] = As[(rb + 8) * PW + kb + t];
                a[mt][2] = As[rb * PW + kb + t + 4];
                a[mt][3] = As[(rb + 8) * PW + kb + t + 4];
            }
#pragma unroll
            for (int nt = 0; nt < 4; nt++) {
                int col = warpN * 32 + nt * 8 + g;
                uint32_t b0 = Bs[col * PW + kb + t];
                uint32_t b1 = Bs[col * PW + kb + t + 4];
#pragma unroll
                for (int mt = 0; mt < 2; mt++) {
                    asm volatile(
                        "mma.sync.aligned.m16n8k16.row.col.f32.f16.f16.f32 "
                        "{%0,%1,%2,%3}, {%4,%5,%6,%7}, {%8,%9}, {%0,%1,%2,%3};"
                        : "+f"(acc[mt][nt][0]), "+f"(acc[mt][nt][1]),
                          "+f"(acc[mt][nt][2]), "+f"(acc[mt][nt][3])
                        : "r"(a[mt][0]), "r"(a[mt][1]), "r"(a[mt][2]), "r"(a[mt][3]),
                          "r"(b0), "r"(b1));
                }
            }
        }

        // store xt[graph][r] as fp16 (pack pairs; col stride 2 -> one u32)
        uint32_t* xt = (uint32_t*)g_xt + (size_t)(graph * RR + r) * NN * 64;
#pragma unroll
        for (int mt = 0; mt < 2; mt++) {
            int row0 = m0 + warpM * 32 + mt * 16 + g;
#pragma unroll
            for (int nt = 0; nt < 4; nt++) {
                int col2 = warpN * 16 + nt * 4 + t;   // (col pair index)
                if (row0 < NN)
                    xt[(size_t)row0 * 64 + col2] =
                        pack_f16x2(acc[mt][nt][0], acc[mt][nt][1]);
                if (row0 + 8 < NN)
                    xt[(size_t)(row0 + 8) * 64 + col2] =
                        pack_f16x2(acc[mt][nt][2], acc[mt][nt][3]);
            }
        }
    }
}

// ---------------- edge pass: denom += ex; acc[dst] += ex * xt[r,src] --------
// 16 lanes per edge: each lane loads uint4 = 8 fp16 cols, 2 red.v4 stores.
__global__ void edge_kernel(const int* __restrict__ ei1, const int* __restrict__ et1,
                            const int* __restrict__ ei2, const int* __restrict__ et2) {
    int graph = blockIdx.y;
    const int* ei = graph ? ei2 : ei1;
    const int* et = graph ? et2 : et1;
    int idx = blockIdx.x * 256 + threadIdx.x;
    int e = idx >> 4;
    if (e >= EE) return;
    int lane16 = threadIdx.x & 15;
    int src = __ldg(ei + e);
    int dst = __ldg(ei + EE + e);
    int r = __ldg(et + e);
    float al = g_qi[(graph * NN + dst) * RR + r] + g_kj[(graph * NN + src) * RR + r];
    al = al > 0.f ? al : 0.2f * al;           // leaky_relu
    float ex = __expf(al);                    // alpha ~ O(1): no max-shift
    if (lane16 == 0) atomicAdd(&g_denom[graph * NN + dst], ex);
    const uint4* xt4 = g_xt + ((size_t)(graph * RR + r) * NN + src) * 16;
    uint4 u = __ldg(&xt4[lane16]);
    float2 p0 = unpack_f16x2(u.x), p1 = unpack_f16x2(u.y);
    float2 p2 = unpack_f16x2(u.z), p3 = unpack_f16x2(u.w);
    float* p = &g_acc[((size_t)graph * NN + dst) * HD + lane16 * 8];
    asm volatile("red.global.add.v4.f32 [%0], {%1,%2,%3,%4};"
                 :: "l"(p), "f"(ex * p0.x), "f"(ex * p0.y),
                    "f"(ex * p1.x), "f"(ex * p1.y) : "memory");
    asm volatile("red.global.add.v4.f32 [%0], {%1,%2,%3,%4};"
                 :: "l"(p + 4), "f"(ex * p2.x), "f"(ex * p2.y),
                    "f"(ex * p3.x), "f"(ex * p3.y) : "memory");
}

// ---------------- out = relu(acc/denom + b) ---------------------------------
__global__ void epilogue_kernel(const float* __restrict__ b1,
                                const float* __restrict__ b2,
                                float* __restrict__ out) {
    int graph = blockIdx.y;
    const float* bias = graph ? b2 : b1;
    int i = blockIdx.x * blockDim.x + threadIdx.x;   // over NN*32 float4s
    if (i >= NN * 32) return;
    int n = i >> 5, c4 = i & 31;
    float inv = 1.0f / (g_denom[graph * NN + n] + 1e-16f);
    float4 v = ((const float4*)g_acc)[(size_t)graph * NN * 32 + i];
    float4 bb = ((const float4*)bias)[c4];
    v.x = fmaxf(v.x * inv + bb.x, 0.f);
    v.y = fmaxf(v.y * inv + bb.y, 0.f);
    v.z = fmaxf(v.z * inv + bb.z, 0.f);
    v.w = fmaxf(v.w * inv + bb.w, 0.f);
    ((float4*)out)[(size_t)graph * NN * 32 + i] = v;
}

// ---------------- driver ----------------------------------------------------
extern "C" void kernel_launch(void* const* d_in, const int* in_sizes, int n_in,
                              void* d_out, int out_size) {
    const float* x1  = (const float*)d_in[0];
    const int*   ei1 = (const int*)d_in[1];
    const int*   et1 = (const int*)d_in[2];
    const float* x2  = (const float*)d_in[3];
    const int*   ei2 = (const int*)d_in[4];
    const int*   et2 = (const int*)d_in[5];
    const float* W1  = (const float*)d_in[6];
    const float* q1  = (const float*)d_in[7];
    const float* k1  = (const float*)d_in[8];
    const float* b1  = (const float*)d_in[9];
    const float* W2  = (const float*)d_in[10];
    const float* q2  = (const float*)d_in[11];
    const float* k2  = (const float*)d_in[12];
    const float* b2  = (const float*)d_in[13];
    float* out = (float*)d_out;

    cudaFuncSetAttribute(xt_gemm, cudaFuncAttributeMaxDynamicSharedMemorySize,
                         GEMM_SMEM);

    prep_kernel<<<2048, 256>>>();
    wqwk_kernel<<<dim3((RR * HD) / 8, NG), 256>>>(W1, q1, k1, W2, q2, k2);
    table_kernel<<<dim3((NN + 7) / 8, NG), 256>>>(x1, x2);
    xt_gemm<<<dim3(MBLK, NG), 256, GEMM_SMEM>>>(x1, x2, W1, W2);
    edge_kernel<<<dim3(EE / 16, NG), 256>>>(ei1, et1, ei2, et2);
    epilogue_kernel<<<dim3((NN * 32 + 255) / 256, NG), 256>>>(b1, b2, out);
}